// round 8
// baseline (speedup 1.0000x reference)
#include <cuda_runtime.h>
#include <cuda_bf16.h>
#include <cstdint>

// I=16, O=8, J=4, B=16 -> n_in=1024, n_out=256, K=81 projectors.
// Output quad index u fields: gc=u[0:5] (i_c*8+j_c), ch=u[6:7], ij_r=u[8:13],
// b=u[14:17]. Source base quad index is a 4-shift bit-permutation of u:
//   base = ((u&7)<<1) + ((u&0xF8)<<2) + ((u&0x700)<<3) + ((u&0x3F800)<<4)
// and the 4 source quads sit at CONSTANT offsets from base:
//   B=+0 (iff i&j match), C=+1025 (iff i match), D=+16400 (iff j match),
//   center=+17425 (always). 49/64 quads need only the center load.
//
// This version processes the ch-bit-0 PAIR (u, u+64) per thread: both quads
// share the same gc/ij_r fields -> identical predicates and address math;
// the second base is just base+256. Per-quad instruction count drops ~40%
// and the two center loads are independent (MLP=2 minimum).

__global__ __launch_bounds__(128, 16)
void pool2d_density_kernel(const float4* __restrict__ xq, float4* __restrict__ oq)
{
    const unsigned tid = threadIdx.x;                  // 0..127
    const unsigned bid = blockIdx.x;                   // 0..1023

    // block covers output quads [bid*256, bid*256+256); thread takes
    // u0 = bid*256 + (tid&63) + ((tid>>6)<<7)  and  u1 = u0 + 64 (ch pair)
    const unsigned u0 = bid * 256u + (tid & 63u) + ((tid >> 6) << 7);
    const unsigned u1 = u0 + 64u;

    // predicates depend only on bits 0-5 and 8-13 of u0 (same for u1);
    // the bid-side operands are warp-uniform.
    const bool im = ((u0 >> 11) & 7u) == ((u0 >> 3) & 7u);   // i_r == i_c
    const bool jm = ((u0 >> 8)  & 7u) == (u0 & 7u);          // j_r == j_c

    // 4-shift bit permutation -> base quad index into X (u1's base = +256)
    const unsigned base = ((u0 & 7u)       << 1)
                        + ((u0 & 0xF8u)    << 2)
                        + ((u0 & 0x700u)   << 3)
                        + ((u0 & 0x3F800u) << 4);

    const float4* __restrict__ p = xq + base;

    // two independent center loads, issued back-to-back
    float4 a0 = __ldg(p + 17425);
    float4 a1 = __ldg(p + 17425 + 256);

    if (im) {                                          // C group
        float4 c0 = __ldg(p + 1025);
        float4 c1 = __ldg(p + 1025 + 256);
        a0.x += c0.x; a0.y += c0.y; a0.z += c0.z; a0.w += c0.w;
        a1.x += c1.x; a1.y += c1.y; a1.z += c1.z; a1.w += c1.w;
    }
    if (jm) {                                          // D group
        float4 d0 = __ldg(p + 16400);
        float4 d1 = __ldg(p + 16400 + 256);
        a0.x += d0.x; a0.y += d0.y; a0.z += d0.z; a0.w += d0.w;
        a1.x += d1.x; a1.y += d1.y; a1.z += d1.z; a1.w += d1.w;
    }
    if (im && jm) {                                    // B group
        float4 b0 = __ldg(p);
        float4 b1 = __ldg(p + 256);
        a0.x += b0.x; a0.y += b0.y; a0.z += b0.z; a0.w += b0.w;
        a1.x += b1.x; a1.y += b1.y; a1.z += b1.z; a1.w += b1.w;
    }

    // store addresses == u0, u1; each warp writes two contiguous 512B runs
    oq[u0] = a0;
    oq[u1] = a1;
}

extern "C" void kernel_launch(void* const* d_in, const int* in_sizes, int n_in,
                              void* d_out, int out_size)
{
    const float4* x = (const float4*)d_in[0];   // (16, 1024, 1024) fp32 as quads
    float4* out = (float4*)d_out;               // (16, 256, 256) fp32 as quads

    // 131072 threads, 2 output quads each: 1024 blocks x 128 threads
    // (~6.9 blocks/SM, ~28 warps/SM, single wave).
    pool2d_density_kernel<<<1024, 128>>>(x, out);
}

// round 9
// speedup vs baseline: 1.0437x; 1.0437x over previous
#include <cuda_runtime.h>
#include <cuda_bf16.h>
#include <cstdint>

// Pooling_2D_density_3D: out[b] = sum_k P_k X P_k^T, K=81 one-hot projectors,
// I=16, O=8, J=4, B=16 -> X:(16,1024,1024), out:(16,256,256).
//
// Closed form (derived from the projector generator, verified rel_err 1.2e-8):
// each output quad is a sum of 1-4 gathered input quads. With u = global
// thread id == linear output float4 index, fields
//   u = b<<12 | ij_r<<6 | ch<<... : gc=u[0:5], ch=u[6:7], ij_r=u[8:13], b=u[14:17]
// the common source base (quad units) is a 4-shift bit-permutation of u:
//   base = ((u&7)<<1) + ((u&0xF8)<<2) + ((u&0x700)<<3) + ((u&0x3F800)<<4)
// and the four source quads sit at CONSTANT offsets from base:
//   B      = base + 0      iff (i_r==i_c && j_r==j_c)
//   C      = base + 1025   iff (i_r==i_c)
//   D      = base + 16400  iff (j_r==j_c)
//   center = base + 17425  always
// 49/64 threads execute only the center load (~15 dynamic instructions).
//
// After 8 optimization rounds (MLP scaling, branch-free masked-FMA,
// unconditional loads, f32x2 packing, ch-pair amortization, grid shapes),
// all variants land 6.2-6.9us: the kernel sits on the launch/ramp/DVFS floor,
// with ~1.5us of actual memory work. This is the converged minimal form.

__global__ __launch_bounds__(256, 8)
void pool2d_density_kernel(const float4* __restrict__ xq, float4* __restrict__ oq)
{
    const unsigned tid = threadIdx.x;
    const unsigned bid = blockIdx.x;
    const unsigned u   = bid * 256u + tid;             // output quad index

    // match predicates straight from launch registers (bid side warp-uniform):
    // im: u[11:13]==u[3:5] -> (bid>>3)&7 vs (tid>>3)&7
    // jm: u[8:10]==u[0:2]  ->  bid&7     vs  tid&7
    const bool im = ((bid >> 3) & 7u) == ((tid >> 3) & 7u);
    const bool jm = (bid & 7u) == (tid & 7u);

    // 4-shift bit permutation -> source base quad index
    const unsigned base = ((u & 7u)       << 1)
                        + ((u & 0xF8u)    << 2)
                        + ((u & 0x700u)   << 3)
                        + ((u & 0x3F800u) << 4);

    const float4* __restrict__ p = xq + base;

    // center term: always present, issued at minimum depth
    float4 acc = __ldg(p + 17425);

    if (im) {                                   // C group (8/64 threads)
        float4 v = __ldg(p + 1025);
        if (jm) {                               // B group (1/64 threads)
            float4 w = __ldg(p);
            v.x += w.x; v.y += w.y; v.z += w.z; v.w += w.w;
        }
        acc.x += v.x; acc.y += v.y; acc.z += v.z; acc.w += v.w;
    }
    if (jm) {                                   // D group (8/64 threads)
        float4 v = __ldg(p + 16400);
        acc.x += v.x; acc.y += v.y; acc.z += v.z; acc.w += v.w;
    }

    // store address == u: fully coalesced 128B stores per warp
    oq[u] = acc;
}

extern "C" void kernel_launch(void* const* d_in, const int* in_sizes, int n_in,
                              void* d_out, int out_size)
{
    const float4* x = (const float4*)d_in[0];   // (16, 1024, 1024) fp32 as quads
    float4* out = (float4*)d_out;               // (16, 256, 256) fp32 as quads

    // 262144 output quads, 1 per thread: 1024 blocks x 256 threads
    // (~7 blocks/SM, single wave) — empirically the best launch shape.
    pool2d_density_kernel<<<1024, 256>>>(x, out);
}